// round 4
// baseline (speedup 1.0000x reference)
#include <cuda_runtime.h>

// ---------------------------------------------------------------------------
// Problem constants
// ---------------------------------------------------------------------------
#define BATCH 64
#define SEQ   512
#define DIM   768
#define BD    (BATCH * DIM)          // 49152
#define R192  192
#define KDIM  1536
#define PREDK 2304

#define KS_FC1  6                    // 1536 = 6 * 256
#define KS_GATE 4                    // 1536 = 4 * 384
#define KS_PRED 12                   // 2304 = 12 * 192

#define FC1_MN  (R192 * 512)         // 98304
#define GATE_MN (R192 * 768)         // 147456
#define PRED_MN (BATCH * 512)        // 32768

// ---------------------------------------------------------------------------
// Device scratch
// ---------------------------------------------------------------------------
__device__ float g_ent  [BATCH * PREDK];       // (B,3,D) flat for pred head
__device__ float g_e    [3 * BD];              // entity state [p][b][d], in-place
__device__ float g_X1   [R192 * KDIM];         // fc1 input  [eA | eB]
__device__ float g_X2   [R192 * KDIM];         // gate input [u  | e ]
__device__ float g_pfc1 [KS_FC1  * FC1_MN];
__device__ float g_pgate[KS_GATE * GATE_MN];
__device__ float g_ppred[KS_PRED * PRED_MN];

__device__ unsigned int g_bar_count = 0;
__device__ unsigned int g_bar_gen   = 0;

// ---------------------------------------------------------------------------
// Helpers
// ---------------------------------------------------------------------------
__device__ __forceinline__ unsigned long long pack2(float x, float y) {
    unsigned long long r;
    asm("mov.b64 %0, {%1, %2};" : "=l"(r) : "f"(x), "f"(y));
    return r;
}
__device__ __forceinline__ void ffma2(unsigned long long& acc,
                                      unsigned long long a,
                                      unsigned long long b) {
    asm("fma.rn.f32x2 %0, %1, %2, %3;" : "=l"(acc) : "l"(a), "l"(b), "l"(acc));
}
__device__ __forceinline__ float2 unpack2(unsigned long long v) {
    float2 f;
    asm("mov.b64 {%0, %1}, %2;" : "=f"(f.x), "=f"(f.y) : "l"(v));
    return f;
}
__device__ __forceinline__ float sigmoidf(float x) {
    return 1.0f / (1.0f + expf(-x));
}
__device__ __forceinline__ float4 ldcg4(const float* p) {
    return __ldcg(reinterpret_cast<const float4*>(p));
}
__device__ __forceinline__ void stcg4(float* p, float4 v) {
    __stcg(reinterpret_cast<float4*>(p), v);
}

// acquire/release primitives for the grid barrier
__device__ __forceinline__ unsigned int atom_add_release(unsigned int* p, unsigned int v) {
    unsigned int r;
    asm volatile("atom.release.gpu.add.u32 %0, [%1], %2;"
                 : "=r"(r) : "l"(p), "r"(v) : "memory");
    return r;
}
__device__ __forceinline__ unsigned int ld_acquire(unsigned int* p) {
    unsigned int r;
    asm volatile("ld.acquire.gpu.u32 %0, [%1];" : "=r"(r) : "l"(p) : "memory");
    return r;
}
__device__ __forceinline__ void st_release(unsigned int* p, unsigned int v) {
    asm volatile("st.release.gpu.u32 [%0], %1;" :: "l"(p), "r"(v) : "memory");
}

// Grid barrier (cooperative-groups semantics; all blocks resident & uniform)
__device__ __forceinline__ void grid_sync() {
    __syncthreads();
    if (threadIdx.x == 0) {
        unsigned int gen = ld_acquire(&g_bar_gen);
        unsigned int t = atom_add_release(&g_bar_count, 1u);
        if (t == gridDim.x - 1u) {
            g_bar_count = 0u;                      // ordered before release below
            st_release(&g_bar_gen, gen + 1u);
        } else {
            while (ld_acquire(&g_bar_gen) == gen) { __nanosleep(40); }
        }
    }
    __syncthreads();
}

// ---------------------------------------------------------------------------
// GEMM tile: C[64x64] = A[64 x kchunk] * W[kchunk x N-tile]
// A pre-offset to (m0 row, k0 col), row-major lda. W pre-offset to (k0,n0).
// Pout pre-offset to tile base (row stride N). Mutable data via ldcg/stcg.
// ---------------------------------------------------------------------------
#define BKT 32

__device__ void gemm_tile(const float* __restrict__ A, int lda,
                          const float* __restrict__ W, int N,
                          float* __restrict__ Pout, int kchunk)
{
    __shared__ float As[BKT][64 + 4];
    __shared__ float Bs[BKT][64 + 4];

    int tid = threadIdx.x;
    int tx = tid & 15;
    int ty = tid >> 4;
    int arow = tid >> 2;
    int aqc  = (tid & 3) * 4;
    int brow = tid >> 3;
    int bqc  = (tid & 7) * 4;

    unsigned long long acc[4][2];
    #pragma unroll
    for (int i = 0; i < 4; i++) { acc[i][0] = 0ULL; acc[i][1] = 0ULL; }

    const float* ap = A + (size_t)arow * lda;

    for (int kb = 0; kb < kchunk; kb += BKT) {
        float4 a0 = ldcg4(ap + kb + aqc);
        float4 a1 = ldcg4(ap + kb + aqc + 16);
        const float* wp = W + (size_t)(kb + brow) * N;
        float4 b0 = *(const float4*)(wp + bqc);
        float4 b1 = *(const float4*)(wp + bqc + 32);

        __syncthreads();
        As[aqc + 0][arow] = a0.x;  As[aqc + 1][arow] = a0.y;
        As[aqc + 2][arow] = a0.z;  As[aqc + 3][arow] = a0.w;
        As[aqc + 16][arow] = a1.x; As[aqc + 17][arow] = a1.y;
        As[aqc + 18][arow] = a1.z; As[aqc + 19][arow] = a1.w;
        *(float4*)&Bs[brow][bqc]      = b0;
        *(float4*)&Bs[brow][bqc + 32] = b1;
        __syncthreads();

        #pragma unroll
        for (int kk = 0; kk < BKT; kk++) {
            float4 av = *(const float4*)&As[kk][ty * 4];
            float4 bv = *(const float4*)&Bs[kk][tx * 4];
            unsigned long long b01 = pack2(bv.x, bv.y);
            unsigned long long b23 = pack2(bv.z, bv.w);
            unsigned long long am;
            am = pack2(av.x, av.x); ffma2(acc[0][0], am, b01); ffma2(acc[0][1], am, b23);
            am = pack2(av.y, av.y); ffma2(acc[1][0], am, b01); ffma2(acc[1][1], am, b23);
            am = pack2(av.z, av.z); ffma2(acc[2][0], am, b01); ffma2(acc[2][1], am, b23);
            am = pack2(av.w, av.w); ffma2(acc[3][0], am, b01); ffma2(acc[3][1], am, b23);
        }
    }

    #pragma unroll
    for (int m = 0; m < 4; m++) {
        float2 c0 = unpack2(acc[m][0]);
        float2 c1 = unpack2(acc[m][1]);
        stcg4(Pout + (size_t)(ty * 4 + m) * N + tx * 4,
              make_float4(c0.x, c0.y, c1.x, c1.y));
    }
}

// ---------------------------------------------------------------------------
// X1 slot tables: entity k appears at (pair D1ROW, col off D1OFF) and
// (pair D2ROW, off D2OFF).  Pairs: p0=[e1|e2], p1=[e0|e2], p2=[e0|e1]
// ---------------------------------------------------------------------------
__device__ __constant__ int D1ROW[3] = {1, 0, 0};
__device__ __constant__ int D1OFF[3] = {0, 0, 768};
__device__ __constant__ int D2ROW[3] = {2, 2, 1};
__device__ __constant__ int D2OFF[3] = {0, 768, 768};

// ---------------------------------------------------------------------------
// Phase jobs
// ---------------------------------------------------------------------------
__device__ void maxpool_job(int bk, const float* __restrict__ enc,
                            const int* __restrict__ ep,
                            const float* __restrict__ projW,
                            const float* __restrict__ projb,
                            float* __restrict__ out_score)
{
    __shared__ float red[256];
    int b = bk / 3, k = bk - b * 3;
    int t = threadIdx.x;
    int s0 = ep[bk * 2 + 0];
    int s1 = ep[bk * 2 + 1];

    float m0 = -1e30f, m1 = -1e30f, m2 = -1e30f;
    const float* base = enc + (size_t)b * SEQ * DIM;
    #pragma unroll 4
    for (int s = s0; s <= s1; s++) {
        const float* row = base + s * DIM;
        m0 = fmaxf(m0, __ldg(row + t));
        m1 = fmaxf(m1, __ldg(row + t + 256));
        m2 = fmaxf(m2, __ldg(row + t + 512));
    }

    size_t x1a = (size_t)(D1ROW[k] * 64 + b) * KDIM + D1OFF[k];
    size_t x1b = (size_t)(D2ROW[k] * 64 + b) * KDIM + D2OFF[k];
    size_t x2r = (size_t)(k * 64 + b) * KDIM + 768;
    size_t er  = (size_t)(k * 64 + b) * DIM;
    size_t eno = (size_t)b * PREDK + k * DIM;

    #pragma unroll
    for (int q = 0; q < 3; q++) {
        int d = t + q * 256;
        float m = (q == 0) ? m0 : (q == 1) ? m1 : m2;
        __stcg(g_ent + eno + d, m);
        __stcg(g_e   + er  + d, m);
        __stcg(g_X1  + x1a + d, m);
        __stcg(g_X1  + x1b + d, m);
        __stcg(g_X2  + x2r + d, m);
    }

    float loc = m0 * projW[t] + m1 * projW[t + 256] + m2 * projW[t + 512];
    red[t] = loc;
    __syncthreads();
    for (int off = 128; off > 0; off >>= 1) {
        if (t < off) red[t] += red[t + off];
        __syncthreads();
    }
    if (t == 0) out_score[bk] = sigmoidf(red[0] + projb[0]);
    __syncthreads();
}

__device__ void finish1_job(int r, const float* __restrict__ b1,
                            const float* __restrict__ W2, const float* __restrict__ b2,
                            const float* __restrict__ ArW, const float* __restrict__ Arb)
{
    __shared__ float sh_h[512];
    __shared__ float red[5][256];
    __shared__ float sh_s[5];
    int t = threadIdx.x;

    for (int j = t; j < 512; j += 256) {
        float s = b1[j];
        #pragma unroll
        for (int z = 0; z < KS_FC1; z++)
            s += __ldcg(g_pfc1 + (size_t)z * FC1_MN + r * 512 + j);
        sh_h[j] = fmaxf(s, 0.0f);
    }
    __syncthreads();

    float ps[5] = {0, 0, 0, 0, 0};
    for (int j = t; j < 512; j += 256) {
        float h = sh_h[j];
        #pragma unroll
        for (int c = 0; c < 5; c++) ps[c] += h * W2[j * 5 + c];
    }
    #pragma unroll
    for (int c = 0; c < 5; c++) red[c][t] = ps[c];
    __syncthreads();
    for (int off = 128; off > 0; off >>= 1) {
        if (t < off) {
            #pragma unroll
            for (int c = 0; c < 5; c++) red[c][t] += red[c][t + off];
        }
        __syncthreads();
    }
    if (t < 5) sh_s[t] = sigmoidf(red[t][0] + b2[t]);
    __syncthreads();

    float s0 = sh_s[0], s1 = sh_s[1], s2 = sh_s[2], s3 = sh_s[3], s4 = sh_s[4];
    const float* epv = g_e + (size_t)r * DIM;
    float* up = g_X2 + (size_t)r * KDIM;          // u -> left half of X2
    for (int d = t; d < DIM; d += 256) {
        float a = Arb[d] + s0 * ArW[d] + s1 * ArW[DIM + d] + s2 * ArW[2 * DIM + d]
                + s3 * ArW[3 * DIM + d] + s4 * ArW[4 * DIM + d];
        __stcg(up + d, a * __ldcg(epv + d));
    }
    __syncthreads();
}

__device__ void pred_finish_job(int b, const float* __restrict__ b1,
                                const float* __restrict__ W2,
                                const float* __restrict__ b2,
                                float* __restrict__ rel_out)
{
    __shared__ float sh_h2[512];
    __shared__ float red2[5][256];
    int t = threadIdx.x;

    for (int j = t; j < 512; j += 256) {
        float s = b1[j];
        #pragma unroll
        for (int z = 0; z < KS_PRED; z++)
            s += __ldcg(g_ppred + (size_t)z * PRED_MN + b * 512 + j);
        sh_h2[j] = fmaxf(s, 0.0f);
    }
    __syncthreads();

    float ps[5] = {0, 0, 0, 0, 0};
    for (int j = t; j < 512; j += 256) {
        float h = sh_h2[j];
        #pragma unroll
        for (int c = 0; c < 5; c++) ps[c] += h * W2[j * 5 + c];
    }
    #pragma unroll
    for (int c = 0; c < 5; c++) red2[c][t] = ps[c];
    __syncthreads();
    for (int off = 128; off > 0; off >>= 1) {
        if (t < off) {
            #pragma unroll
            for (int c = 0; c < 5; c++) red2[c][t] += red2[c][t + off];
        }
        __syncthreads();
    }
    if (t < 5) rel_out[b * 5 + t] = red2[t][0] + b2[t];
    __syncthreads();
}

// ---------------------------------------------------------------------------
// Persistent fused kernel
// ---------------------------------------------------------------------------
__global__ void __launch_bounds__(256, 1)
fused_kernel(const float* __restrict__ enc, const int* __restrict__ ep,
             const float* __restrict__ ArW, const float* __restrict__ Arb,
             const float* __restrict__ VrW1, const float* __restrict__ Vrb1,
             const float* __restrict__ VrW2, const float* __restrict__ Vrb2,
             const float* __restrict__ gateW, const float* __restrict__ gateb,
             const float* __restrict__ predW1, const float* __restrict__ predb1,
             const float* __restrict__ predW2, const float* __restrict__ predb2,
             const float* __restrict__ projW, const float* __restrict__ projb,
             float* __restrict__ out_rel, float* __restrict__ out_score,
             float* __restrict__ out_final)
{
    const int nb = gridDim.x;

    // ---- Phase 0: span max-pool (+ scores, X1/X2 init) ----
    for (int job = blockIdx.x; job < R192; job += nb)
        maxpool_job(job, enc, ep, projW, projb, out_score);
    grid_sync();

    for (int it = 0; it < 5; it++) {
        // ---- P1: fc1 GEMM partials (+ pred GEMM on iter 0) ----
        int nj = (it == 0) ? 240 : 144;
        for (int job = blockIdx.x; job < nj; job += nb) {
            if (job < 144) {
                int z = job / 24, rem = job % 24;
                int m0 = (rem >> 3) * 64, n0 = (rem & 7) * 64;
                int k0 = z * 256;
                gemm_tile(g_X1 + (size_t)m0 * KDIM + k0, KDIM,
                          VrW1 + (size_t)k0 * 512 + n0, 512,
                          g_pfc1 + (size_t)z * FC1_MN + m0 * 512 + n0, 256);
            } else {
                int j = job - 144;                 // 0..95
                int z = j >> 3, n0 = (j & 7) * 64;
                int k0 = z * 192;
                gemm_tile(g_ent + k0, PREDK,
                          predW1 + (size_t)k0 * 512 + n0, 512,
                          g_ppred + (size_t)z * PRED_MN + n0, 192);
            }
        }
        grid_sync();

        // ---- P2: fc1 finish -> u (X2 left half) (+ pred finish on iter 0) ----
        nj = (it == 0) ? 256 : 192;
        for (int job = blockIdx.x; job < nj; job += nb) {
            if (job < 192) finish1_job(job, Vrb1, VrW2, Vrb2, ArW, Arb);
            else           pred_finish_job(job - 192, predb1, predW2, predb2, out_rel);
        }
        grid_sync();

        // ---- P3: gate GEMM partials from X2 ----
        for (int job = blockIdx.x; job < 144; job += nb) {
            int z = job / 36, rem = job % 36;
            int m0 = (rem / 12) * 64, n0 = (rem % 12) * 64;
            int k0 = z * 384;
            gemm_tile(g_X2 + (size_t)m0 * KDIM + k0, KDIM,
                      gateW + (size_t)k0 * 768 + n0, 768,
                      g_pgate + (size_t)z * GATE_MN + m0 * 768 + n0, 384);
        }
        grid_sync();

        // ---- P4: gate blend; in-place e update + X1/X2 scatter; last -> out ----
        bool last = (it == 4);
        int tg = blockIdx.x * 256 + threadIdx.x;
        for (int q = tg; q < GATE_MN / 4; q += nb * 256) {
            int idx = q * 4;
            int r = idx / 768, n = idx - r * 768;
            int p = r >> 6, b = r & 63;
            float4 s = *(const float4*)(gateb + n);
            #pragma unroll
            for (int z = 0; z < KS_GATE; z++) {
                float4 pv = ldcg4(g_pgate + (size_t)z * GATE_MN + idx);
                s.x += pv.x; s.y += pv.y; s.z += pv.z; s.w += pv.w;
            }
            float4 uv = ldcg4(g_X2 + (size_t)r * KDIM + n);   // u (left half)
            float4 ev = ldcg4(g_e + idx);
            float4 res; float gg;
            gg = sigmoidf(s.x); res.x = gg * ev.x + (1.0f - gg) * uv.x;
            gg = sigmoidf(s.y); res.y = gg * ev.y + (1.0f - gg) * uv.y;
            gg = sigmoidf(s.z); res.z = gg * ev.z + (1.0f - gg) * uv.z;
            gg = sigmoidf(s.w); res.w = gg * ev.w + (1.0f - gg) * uv.w;
            if (last) {
                *(float4*)(out_final + (size_t)b * PREDK + p * DIM + n) = res;
            } else {
                stcg4(g_e + idx, res);
                stcg4(g_X2 + (size_t)r * KDIM + 768 + n, res);
                stcg4(g_X1 + (size_t)(D1ROW[p] * 64 + b) * KDIM + D1OFF[p] + n, res);
                stcg4(g_X1 + (size_t)(D2ROW[p] * 64 + b) * KDIM + D2OFF[p] + n, res);
            }
        }
        if (!last) grid_sync();
    }
}

// ---------------------------------------------------------------------------
// Launcher
// ---------------------------------------------------------------------------
extern "C" void kernel_launch(void* const* d_in, const int* in_sizes, int n_in,
                              void* d_out, int out_size)
{
    const float* encoding = (const float*)d_in[0];
    const int*   ent_pos  = (const int*)  d_in[1];
    const float* Ar_W     = (const float*)d_in[2];
    const float* Ar_b     = (const float*)d_in[3];
    const float* Vr_W1    = (const float*)d_in[4];
    const float* Vr_b1    = (const float*)d_in[5];
    const float* Vr_W2    = (const float*)d_in[6];
    const float* Vr_b2    = (const float*)d_in[7];
    const float* gate_W   = (const float*)d_in[8];
    const float* gate_b   = (const float*)d_in[9];
    const float* pred_W1  = (const float*)d_in[10];
    const float* pred_b1  = (const float*)d_in[11];
    const float* pred_W2  = (const float*)d_in[12];
    const float* pred_b2  = (const float*)d_in[13];
    const float* proj_W   = (const float*)d_in[14];
    const float* proj_b   = (const float*)d_in[15];

    float* out = (float*)d_out;
    float* out_rel   = out;              // (64,5)
    float* out_score = out + 320;        // (64,3)
    float* out_final = out + 512;        // (64,3,768)

    int dev = 0;
    cudaGetDevice(&dev);
    int sms = 148;
    cudaDeviceGetAttribute(&sms, cudaDevAttrMultiProcessorCount, dev);

    fused_kernel<<<sms, 256>>>(encoding, ent_pos, Ar_W, Ar_b,
                               Vr_W1, Vr_b1, Vr_W2, Vr_b2,
                               gate_W, gate_b,
                               pred_W1, pred_b1, pred_W2, pred_b2,
                               proj_W, proj_b,
                               out_rel, out_score, out_final);

    (void)in_sizes; (void)n_in; (void)out_size;
}

// round 5
// speedup vs baseline: 1.1069x; 1.1069x over previous
#include <cuda_runtime.h>

// ---------------------------------------------------------------------------
// Problem constants
// ---------------------------------------------------------------------------
#define BATCH 64
#define SEQ   512
#define DIM   768
#define BD    (BATCH * DIM)          // 49152
#define R192  192
#define KDIM  1536
#define PREDK 2304

#define KS_FC1  12                   // 1536 = 12 * 128
#define KS_GATE 8                    // 1536 = 8 * 192
#define KS_PRED 12                   // 2304 = 12 * 192

#define FC1_MN  (R192 * 512)         // 98304
#define GATE_MN (R192 * 768)         // 147456
#define PRED_MN (BATCH * 512)        // 32768

// ---------------------------------------------------------------------------
// Device scratch
// ---------------------------------------------------------------------------
__device__ float g_ent  [BATCH * PREDK];
__device__ float g_e    [3 * BD];              // entity state, in-place
__device__ float g_X1   [R192 * KDIM];         // fc1 input  [eA | eB]
__device__ float g_X2   [R192 * KDIM];         // gate input [u  | e ]
__device__ float g_pfc1 [KS_FC1  * FC1_MN];
__device__ float g_pgate[KS_GATE * GATE_MN];
__device__ float g_ppred[KS_PRED * PRED_MN];

__device__ unsigned int g_bar_count = 0;
__device__ unsigned int g_bar_gen   = 0;

// ---------------------------------------------------------------------------
// Helpers
// ---------------------------------------------------------------------------
__device__ __forceinline__ unsigned long long pack2(float x, float y) {
    unsigned long long r;
    asm("mov.b64 %0, {%1, %2};" : "=l"(r) : "f"(x), "f"(y));
    return r;
}
__device__ __forceinline__ void ffma2(unsigned long long& acc,
                                      unsigned long long a,
                                      unsigned long long b) {
    asm("fma.rn.f32x2 %0, %1, %2, %3;" : "=l"(acc) : "l"(a), "l"(b), "l"(acc));
}
__device__ __forceinline__ float2 unpack2(unsigned long long v) {
    float2 f;
    asm("mov.b64 {%0, %1}, %2;" : "=f"(f.x), "=f"(f.y) : "l"(v));
    return f;
}
__device__ __forceinline__ float sigmoidf(float x) {
    return 1.0f / (1.0f + expf(-x));
}
__device__ __forceinline__ float4 ldcg4(const float* p) {
    return __ldcg(reinterpret_cast<const float4*>(p));
}
__device__ __forceinline__ void stcg4(float* p, float4 v) {
    __stcg(reinterpret_cast<float4*>(p), v);
}
// per-half (256-thread) barrier: ids 1 and 2
__device__ __forceinline__ void half_sync(int half) {
    asm volatile("bar.sync %0, 256;" :: "r"(half + 1) : "memory");
}

__device__ __forceinline__ unsigned int atom_add_release(unsigned int* p, unsigned int v) {
    unsigned int r;
    asm volatile("atom.release.gpu.add.u32 %0, [%1], %2;"
                 : "=r"(r) : "l"(p), "r"(v) : "memory");
    return r;
}
__device__ __forceinline__ unsigned int ld_acquire(unsigned int* p) {
    unsigned int r;
    asm volatile("ld.acquire.gpu.u32 %0, [%1];" : "=r"(r) : "l"(p) : "memory");
    return r;
}
__device__ __forceinline__ void st_release(unsigned int* p, unsigned int v) {
    asm volatile("st.release.gpu.u32 [%0], %1;" :: "l"(p), "r"(v) : "memory");
}

// Grid barrier over all resident blocks (512 threads each)
__device__ __forceinline__ void grid_sync() {
    __syncthreads();
    if (threadIdx.x == 0) {
        unsigned int gen = ld_acquire(&g_bar_gen);
        unsigned int t = atom_add_release(&g_bar_count, 1u);
        if (t == gridDim.x - 1u) {
            g_bar_count = 0u;
            st_release(&g_bar_gen, gen + 1u);
        } else {
            while (ld_acquire(&g_bar_gen) == gen) { __nanosleep(32); }
        }
    }
    __syncthreads();
}

// ---------------------------------------------------------------------------
// Shared-memory union: per half 17408 bytes
//   GEMM:   As[32][68] (8704 B) + Bs[32][68] (8704 B)
//   finish: sh_h[512] + red[5*256] + sh_s[8]  (7200 B)
//   maxpool: red[256]
// ---------------------------------------------------------------------------
#define HALF_SMEM_BYTES 17408

// ---------------------------------------------------------------------------
// GEMM tile: C[64x64] = A[64 x kchunk] * W[kchunk x N-tile]   (per 256-thr half)
// ---------------------------------------------------------------------------
#define BKT 32

__device__ void gemm_tile(int half, int ht, float* sbase,
                          const float* __restrict__ A, int lda,
                          const float* __restrict__ W, int N,
                          float* __restrict__ Pout, int kchunk)
{
    float (*As)[68] = reinterpret_cast<float(*)[68]>(sbase);
    float (*Bs)[68] = reinterpret_cast<float(*)[68]>(sbase + 32 * 68);

    int tx = ht & 15;
    int ty = ht >> 4;
    int arow = ht >> 2;
    int aqc  = (ht & 3) * 4;
    int brow = ht >> 3;
    int bqc  = (ht & 7) * 4;

    unsigned long long acc[4][2];
    #pragma unroll
    for (int i = 0; i < 4; i++) { acc[i][0] = 0ULL; acc[i][1] = 0ULL; }

    const float* ap = A + (size_t)arow * lda;

    for (int kb = 0; kb < kchunk; kb += BKT) {
        float4 a0 = ldcg4(ap + kb + aqc);
        float4 a1 = ldcg4(ap + kb + aqc + 16);
        const float* wp = W + (size_t)(kb + brow) * N;
        float4 b0 = *(const float4*)(wp + bqc);
        float4 b1 = *(const float4*)(wp + bqc + 32);

        half_sync(half);
        As[aqc + 0][arow] = a0.x;  As[aqc + 1][arow] = a0.y;
        As[aqc + 2][arow] = a0.z;  As[aqc + 3][arow] = a0.w;
        As[aqc + 16][arow] = a1.x; As[aqc + 17][arow] = a1.y;
        As[aqc + 18][arow] = a1.z; As[aqc + 19][arow] = a1.w;
        *(float4*)&Bs[brow][bqc]      = b0;
        *(float4*)&Bs[brow][bqc + 32] = b1;
        half_sync(half);

        #pragma unroll
        for (int kk = 0; kk < BKT; kk++) {
            float4 av = *(const float4*)&As[kk][ty * 4];
            float4 bv = *(const float4*)&Bs[kk][tx * 4];
            unsigned long long b01 = pack2(bv.x, bv.y);
            unsigned long long b23 = pack2(bv.z, bv.w);
            unsigned long long am;
            am = pack2(av.x, av.x); ffma2(acc[0][0], am, b01); ffma2(acc[0][1], am, b23);
            am = pack2(av.y, av.y); ffma2(acc[1][0], am, b01); ffma2(acc[1][1], am, b23);
            am = pack2(av.z, av.z); ffma2(acc[2][0], am, b01); ffma2(acc[2][1], am, b23);
            am = pack2(av.w, av.w); ffma2(acc[3][0], am, b01); ffma2(acc[3][1], am, b23);
        }
    }

    #pragma unroll
    for (int m = 0; m < 4; m++) {
        float2 c0 = unpack2(acc[m][0]);
        float2 c1 = unpack2(acc[m][1]);
        stcg4(Pout + (size_t)(ty * 4 + m) * N + tx * 4,
              make_float4(c0.x, c0.y, c1.x, c1.y));
    }
}

// X1 slot tables. Pairs: p0=[e1|e2], p1=[e0|e2], p2=[e0|e1]
__device__ __constant__ int D1ROW[3] = {1, 0, 0};
__device__ __constant__ int D1OFF[3] = {0, 0, 768};
__device__ __constant__ int D2ROW[3] = {2, 2, 1};
__device__ __constant__ int D2OFF[3] = {0, 768, 768};

// ---------------------------------------------------------------------------
// Phase jobs (per 256-thread half)
// ---------------------------------------------------------------------------
__device__ void maxpool_job(int half, int t, float* sbase, int bk,
                            const float* __restrict__ enc,
                            const int* __restrict__ ep,
                            const float* __restrict__ projW,
                            const float* __restrict__ projb,
                            float* __restrict__ out_score)
{
    float* red = sbase;
    int b = bk / 3, k = bk - b * 3;
    int s0 = ep[bk * 2 + 0];
    int s1 = ep[bk * 2 + 1];

    float m0 = -1e30f, m1 = -1e30f, m2 = -1e30f;
    const float* base = enc + (size_t)b * SEQ * DIM;
    #pragma unroll 4
    for (int s = s0; s <= s1; s++) {
        const float* row = base + s * DIM;
        m0 = fmaxf(m0, __ldg(row + t));
        m1 = fmaxf(m1, __ldg(row + t + 256));
        m2 = fmaxf(m2, __ldg(row + t + 512));
    }

    size_t x1a = (size_t)(D1ROW[k] * 64 + b) * KDIM + D1OFF[k];
    size_t x1b = (size_t)(D2ROW[k] * 64 + b) * KDIM + D2OFF[k];
    size_t x2r = (size_t)(k * 64 + b) * KDIM + 768;
    size_t er  = (size_t)(k * 64 + b) * DIM;
    size_t eno = (size_t)b * PREDK + k * DIM;

    #pragma unroll
    for (int q = 0; q < 3; q++) {
        int d = t + q * 256;
        float m = (q == 0) ? m0 : (q == 1) ? m1 : m2;
        __stcg(g_ent + eno + d, m);
        __stcg(g_e   + er  + d, m);
        __stcg(g_X1  + x1a + d, m);
        __stcg(g_X1  + x1b + d, m);
        __stcg(g_X2  + x2r + d, m);
    }

    red[t] = m0 * projW[t] + m1 * projW[t + 256] + m2 * projW[t + 512];
    half_sync(half);
    for (int off = 128; off > 0; off >>= 1) {
        if (t < off) red[t] += red[t + off];
        half_sync(half);
    }
    if (t == 0) out_score[bk] = sigmoidf(red[0] + projb[0]);
    half_sync(half);
}

__device__ void finish1_job(int half, int t, float* sbase, int r,
                            const float* __restrict__ b1,
                            const float* __restrict__ W2, const float* __restrict__ b2,
                            const float* __restrict__ ArW, const float* __restrict__ Arb)
{
    float* sh_h = sbase;               // 512
    float* red  = sbase + 512;         // 5*256
    float* sh_s = sbase + 512 + 1280;  // 8

    for (int j = t; j < 512; j += 256) {
        float s = b1[j];
        #pragma unroll
        for (int z = 0; z < KS_FC1; z++)
            s += __ldcg(g_pfc1 + (size_t)z * FC1_MN + r * 512 + j);
        sh_h[j] = fmaxf(s, 0.0f);
    }
    half_sync(half);

    float ps[5] = {0, 0, 0, 0, 0};
    for (int j = t; j < 512; j += 256) {
        float h = sh_h[j];
        #pragma unroll
        for (int c = 0; c < 5; c++) ps[c] += h * W2[j * 5 + c];
    }
    #pragma unroll
    for (int c = 0; c < 5; c++) red[c * 256 + t] = ps[c];
    half_sync(half);
    for (int off = 128; off > 0; off >>= 1) {
        if (t < off) {
            #pragma unroll
            for (int c = 0; c < 5; c++) red[c * 256 + t] += red[c * 256 + t + off];
        }
        half_sync(half);
    }
    if (t < 5) sh_s[t] = sigmoidf(red[t * 256] + b2[t]);
    half_sync(half);

    float s0 = sh_s[0], s1 = sh_s[1], s2 = sh_s[2], s3 = sh_s[3], s4 = sh_s[4];
    const float* epv = g_e + (size_t)r * DIM;
    float* up = g_X2 + (size_t)r * KDIM;          // u -> left half of X2
    for (int d = t; d < DIM; d += 256) {
        float a = Arb[d] + s0 * ArW[d] + s1 * ArW[DIM + d] + s2 * ArW[2 * DIM + d]
                + s3 * ArW[3 * DIM + d] + s4 * ArW[4 * DIM + d];
        __stcg(up + d, a * __ldcg(epv + d));
    }
    half_sync(half);
}

__device__ void pred_finish_job(int half, int t, float* sbase, int b,
                                const float* __restrict__ b1,
                                const float* __restrict__ W2,
                                const float* __restrict__ b2,
                                float* __restrict__ rel_out)
{
    float* sh_h = sbase;
    float* red  = sbase + 512;

    for (int j = t; j < 512; j += 256) {
        float s = b1[j];
        #pragma unroll
        for (int z = 0; z < KS_PRED; z++)
            s += __ldcg(g_ppred + (size_t)z * PRED_MN + b * 512 + j);
        sh_h[j] = fmaxf(s, 0.0f);
    }
    half_sync(half);

    float ps[5] = {0, 0, 0, 0, 0};
    for (int j = t; j < 512; j += 256) {
        float h = sh_h[j];
        #pragma unroll
        for (int c = 0; c < 5; c++) ps[c] += h * W2[j * 5 + c];
    }
    #pragma unroll
    for (int c = 0; c < 5; c++) red[c * 256 + t] = ps[c];
    half_sync(half);
    for (int off = 128; off > 0; off >>= 1) {
        if (t < off) {
            #pragma unroll
            for (int c = 0; c < 5; c++) red[c * 256 + t] += red[c * 256 + t + off];
        }
        half_sync(half);
    }
    if (t < 5) rel_out[b * 5 + t] = red[t * 256] + b2[t];
    half_sync(half);
}

// ---------------------------------------------------------------------------
// Persistent fused kernel: 512 threads = two 256-thread job workers
// ---------------------------------------------------------------------------
__global__ void __launch_bounds__(512, 1)
fused_kernel(const float* __restrict__ enc, const int* __restrict__ ep,
             const float* __restrict__ ArW, const float* __restrict__ Arb,
             const float* __restrict__ VrW1, const float* __restrict__ Vrb1,
             const float* __restrict__ VrW2, const float* __restrict__ Vrb2,
             const float* __restrict__ gateW, const float* __restrict__ gateb,
             const float* __restrict__ predW1, const float* __restrict__ predb1,
             const float* __restrict__ predW2, const float* __restrict__ predb2,
             const float* __restrict__ projW, const float* __restrict__ projb,
             float* __restrict__ out_rel, float* __restrict__ out_score,
             float* __restrict__ out_final)
{
    __shared__ __align__(16) float smem_u[2 * HALF_SMEM_BYTES / 4];

    const int half = threadIdx.x >> 8;
    const int ht   = threadIdx.x & 255;
    float* sbase = smem_u + half * (HALF_SMEM_BYTES / 4);

    const int gid     = blockIdx.x * 2 + half;     // worker id
    const int gstride = gridDim.x * 2;             // 296 workers

    // ---- Phase 0: span max-pool (+ scores, X1/X2 init) ----
    for (int job = gid; job < R192; job += gstride)
        maxpool_job(half, ht, sbase, job, enc, ep, projW, projb, out_score);
    grid_sync();

    for (int it = 0; it < 5; it++) {
        // ---- P1: fc1 GEMM partials (288 jobs) + pred GEMM (96 jobs, iter 0) ----
        int nj = (it == 0) ? (288 + 96) : 288;
        for (int job = gid; job < nj; job += gstride) {
            if (job < 288) {
                int z = job / 24, rem = job % 24;
                int m0 = (rem >> 3) * 64, n0 = (rem & 7) * 64;
                int k0 = z * 128;
                gemm_tile(half, ht, sbase,
                          g_X1 + (size_t)m0 * KDIM + k0, KDIM,
                          VrW1 + (size_t)k0 * 512 + n0, 512,
                          g_pfc1 + (size_t)z * FC1_MN + m0 * 512 + n0, 128);
            } else {
                int j = job - 288;                 // 0..95
                int z = j >> 3, n0 = (j & 7) * 64;
                int k0 = z * 192;
                gemm_tile(half, ht, sbase,
                          g_ent + k0, PREDK,
                          predW1 + (size_t)k0 * 512 + n0, 512,
                          g_ppred + (size_t)z * PRED_MN + n0, 192);
            }
        }
        grid_sync();

        // ---- P2: fc1 finish -> u (+ pred finish on iter 0) ----
        nj = (it == 0) ? 256 : 192;
        for (int job = gid; job < nj; job += gstride) {
            if (job < 192) finish1_job(half, ht, sbase, job, Vrb1, VrW2, Vrb2, ArW, Arb);
            else           pred_finish_job(half, ht, sbase, job - 192,
                                           predb1, predW2, predb2, out_rel);
        }
        grid_sync();

        // ---- P3: gate GEMM partials (288 jobs) ----
        for (int job = gid; job < 288; job += gstride) {
            int z = job / 36, rem = job % 36;
            int m0 = (rem / 12) * 64, n0 = (rem % 12) * 64;
            int k0 = z * 192;
            gemm_tile(half, ht, sbase,
                      g_X2 + (size_t)m0 * KDIM + k0, KDIM,
                      gateW + (size_t)k0 * 768 + n0, 768,
                      g_pgate + (size_t)z * GATE_MN + m0 * 768 + n0, 192);
        }
        grid_sync();

        // ---- P4: gate blend; in-place e update + X1/X2 scatter ----
        bool last = (it == 4);
        int tg = blockIdx.x * 512 + threadIdx.x;
        for (int q = tg; q < GATE_MN / 4; q += gridDim.x * 512) {
            int idx = q * 4;
            int r = idx / 768, n = idx - r * 768;
            int p = r >> 6, b = r & 63;
            float4 s = *(const float4*)(gateb + n);
            #pragma unroll
            for (int z = 0; z < KS_GATE; z++) {
                float4 pv = ldcg4(g_pgate + (size_t)z * GATE_MN + idx);
                s.x += pv.x; s.y += pv.y; s.z += pv.z; s.w += pv.w;
            }
            float4 uv = ldcg4(g_X2 + (size_t)r * KDIM + n);   // u (left half)
            float4 ev = ldcg4(g_e + idx);
            float4 res; float gg;
            gg = sigmoidf(s.x); res.x = gg * ev.x + (1.0f - gg) * uv.x;
            gg = sigmoidf(s.y); res.y = gg * ev.y + (1.0f - gg) * uv.y;
            gg = sigmoidf(s.z); res.z = gg * ev.z + (1.0f - gg) * uv.z;
            gg = sigmoidf(s.w); res.w = gg * ev.w + (1.0f - gg) * uv.w;
            if (last) {
                *(float4*)(out_final + (size_t)b * PREDK + p * DIM + n) = res;
            } else {
                stcg4(g_e + idx, res);
                stcg4(g_X2 + (size_t)r * KDIM + 768 + n, res);
                stcg4(g_X1 + (size_t)(D1ROW[p] * 64 + b) * KDIM + D1OFF[p] + n, res);
                stcg4(g_X1 + (size_t)(D2ROW[p] * 64 + b) * KDIM + D2OFF[p] + n, res);
            }
        }
        if (!last) grid_sync();
    }
}

// ---------------------------------------------------------------------------
// Launcher
// ---------------------------------------------------------------------------
extern "C" void kernel_launch(void* const* d_in, const int* in_sizes, int n_in,
                              void* d_out, int out_size)
{
    const float* encoding = (const float*)d_in[0];
    const int*   ent_pos  = (const int*)  d_in[1];
    const float* Ar_W     = (const float*)d_in[2];
    const float* Ar_b     = (const float*)d_in[3];
    const float* Vr_W1    = (const float*)d_in[4];
    const float* Vr_b1    = (const float*)d_in[5];
    const float* Vr_W2    = (const float*)d_in[6];
    const float* Vr_b2    = (const float*)d_in[7];
    const float* gate_W   = (const float*)d_in[8];
    const float* gate_b   = (const float*)d_in[9];
    const float* pred_W1  = (const float*)d_in[10];
    const float* pred_b1  = (const float*)d_in[11];
    const float* pred_W2  = (const float*)d_in[12];
    const float* pred_b2  = (const float*)d_in[13];
    const float* proj_W   = (const float*)d_in[14];
    const float* proj_b   = (const float*)d_in[15];

    float* out = (float*)d_out;
    float* out_rel   = out;              // (64,5)
    float* out_score = out + 320;        // (64,3)
    float* out_final = out + 512;        // (64,3,768)

    int dev = 0;
    cudaGetDevice(&dev);
    int sms = 148;
    cudaDeviceGetAttribute(&sms, cudaDevAttrMultiProcessorCount, dev);

    fused_kernel<<<sms, 512>>>(encoding, ent_pos, Ar_W, Ar_b,
                               Vr_W1, Vr_b1, Vr_W2, Vr_b2,
                               gate_W, gate_b,
                               pred_W1, pred_b1, pred_W2, pred_b2,
                               proj_W, proj_b,
                               out_rel, out_score, out_final);

    (void)in_sizes; (void)n_in; (void)out_size;
}

// round 6
// speedup vs baseline: 1.1745x; 1.0611x over previous
#include <cuda_runtime.h>

// ---------------------------------------------------------------------------
// Problem constants
// ---------------------------------------------------------------------------
#define BATCH 64
#define SEQ   512
#define DIM   768
#define BD    (BATCH * DIM)          // 49152
#define R192  192
#define KDIM  1536
#define PREDK 2304

#define KS_FC1  12                   // 1536 = 12 * 128
#define KS_GATE 8                    // 1536 = 8 * 192
#define KS_PRED 12                   // 2304 = 12 * 192

#define FC1_MN  (R192 * 512)         // 98304
#define GATE_MN (R192 * 768)         // 147456
#define PRED_MN (BATCH * 512)        // 32768

// ---------------------------------------------------------------------------
// Device scratch
// ---------------------------------------------------------------------------
__device__ float g_ent  [BATCH * PREDK];
__device__ float g_e    [3 * BD];              // entity state, in-place
__device__ float g_X1   [R192 * KDIM];         // fc1 input  [eA | eB]
__device__ float g_X2   [R192 * KDIM];         // gate input [u  | e ]
__device__ float g_pfc1 [KS_FC1  * FC1_MN];
__device__ float g_pgate[KS_GATE * GATE_MN];
__device__ float g_ppred[KS_PRED * PRED_MN];

__device__ unsigned int g_bar_count = 0;
__device__ unsigned int g_bar_gen   = 0;

// ---------------------------------------------------------------------------
// Helpers
// ---------------------------------------------------------------------------
__device__ __forceinline__ unsigned long long pack2(float x, float y) {
    unsigned long long r;
    asm("mov.b64 %0, {%1, %2};" : "=l"(r) : "f"(x), "f"(y));
    return r;
}
__device__ __forceinline__ void ffma2(unsigned long long& acc,
                                      unsigned long long a,
                                      unsigned long long b) {
    asm("fma.rn.f32x2 %0, %1, %2, %3;" : "=l"(acc) : "l"(a), "l"(b), "l"(acc));
}
__device__ __forceinline__ float2 unpack2(unsigned long long v) {
    float2 f;
    asm("mov.b64 {%0, %1}, %2;" : "=f"(f.x), "=f"(f.y) : "l"(v));
    return f;
}
__device__ __forceinline__ float sigmoidf(float x) {
    return 1.0f / (1.0f + expf(-x));
}
__device__ __forceinline__ float4 ldcg4(const float* p) {
    return __ldcg(reinterpret_cast<const float4*>(p));
}
__device__ __forceinline__ void stcg4(float* p, float4 v) {
    __stcg(reinterpret_cast<float4*>(p), v);
}
__device__ __forceinline__ float4 ldg4(const float* p) {
    return __ldg(reinterpret_cast<const float4*>(p));
}
// per-half (256-thread) barrier: ids 1 and 2
__device__ __forceinline__ void half_sync(int half) {
    asm volatile("bar.sync %0, 256;" :: "r"(half + 1) : "memory");
}

__device__ __forceinline__ unsigned int atom_add_release(unsigned int* p, unsigned int v) {
    unsigned int r;
    asm volatile("atom.release.gpu.add.u32 %0, [%1], %2;"
                 : "=r"(r) : "l"(p), "r"(v) : "memory");
    return r;
}
__device__ __forceinline__ unsigned int ld_acquire(unsigned int* p) {
    unsigned int r;
    asm volatile("ld.acquire.gpu.u32 %0, [%1];" : "=r"(r) : "l"(p) : "memory");
    return r;
}
__device__ __forceinline__ void st_release(unsigned int* p, unsigned int v) {
    asm volatile("st.release.gpu.u32 [%0], %1;" :: "l"(p), "r"(v) : "memory");
}

// Grid barrier over all resident blocks (512 threads each)
__device__ __forceinline__ void grid_sync() {
    __syncthreads();
    if (threadIdx.x == 0) {
        unsigned int gen = ld_acquire(&g_bar_gen);
        unsigned int t = atom_add_release(&g_bar_count, 1u);
        if (t == gridDim.x - 1u) {
            g_bar_count = 0u;
            st_release(&g_bar_gen, gen + 1u);
        } else {
            while (ld_acquire(&g_bar_gen) == gen) { __nanosleep(32); }
        }
    }
    __syncthreads();
}

// ---------------------------------------------------------------------------
// Dynamic shared memory layout (per 256-thread half):
//   2 stages x (As[32][68] + Bs[32][68]) = 2 x 17408 B = 34816 B
//   finish jobs reuse the first 7.2 KB of the half's region
// ---------------------------------------------------------------------------
#define STAGE_F      4352            // floats per stage (As 2176 + Bs 2176)
#define HALF_SMEM_F  8704            // floats per half (2 stages)
#define TOTAL_SMEM_B (2 * HALF_SMEM_F * 4)   // 69632 bytes

// ---------------------------------------------------------------------------
// Software-pipelined GEMM tile: C[64x64] = A[64 x kchunk] * W[kchunk x Ntile]
// 2-stage smem double buffer; global prefetch of tile t+1 overlapped with
// compute of tile t; ONE half-barrier per k-tile.
// ---------------------------------------------------------------------------
__device__ void gemm_tile(int half, int ht, float* sbase,
                          const float* __restrict__ A, int lda,
                          const float* __restrict__ W, int N,
                          float* __restrict__ Pout, int kchunk)
{
    int tx = ht & 15;
    int ty = ht >> 4;
    int arow = ht >> 2;
    int aqc  = (ht & 3) * 4;
    int brow = ht >> 3;
    int bqc  = (ht & 7) * 4;

    unsigned long long acc[4][2];
    #pragma unroll
    for (int i = 0; i < 4; i++) { acc[i][0] = 0ULL; acc[i][1] = 0ULL; }

    const float* ap = A + (size_t)arow * lda;

    // prologue: load tile 0
    float4 a0 = ldcg4(ap + aqc);
    float4 a1 = ldcg4(ap + aqc + 16);
    const float* wp0 = W + (size_t)brow * N;
    float4 b0 = ldg4(wp0 + bqc);
    float4 b1 = ldg4(wp0 + bqc + 32);

    half_sync(half);                      // previous smem users done
    {
        float* As = sbase;
        float* Bs = sbase + 2176;
        As[(aqc + 0) * 68 + arow] = a0.x;  As[(aqc + 1) * 68 + arow] = a0.y;
        As[(aqc + 2) * 68 + arow] = a0.z;  As[(aqc + 3) * 68 + arow] = a0.w;
        As[(aqc + 16) * 68 + arow] = a1.x; As[(aqc + 17) * 68 + arow] = a1.y;
        As[(aqc + 18) * 68 + arow] = a1.z; As[(aqc + 19) * 68 + arow] = a1.w;
        *(float4*)&Bs[brow * 68 + bqc]      = b0;
        *(float4*)&Bs[brow * 68 + bqc + 32] = b1;
    }
    half_sync(half);

    int T = kchunk >> 5;
    int p = 0;
    for (int t = 0; t < T; t++) {
        // prefetch tile t+1 into registers (latency hidden by compute below)
        if (t + 1 < T) {
            int kb = (t + 1) << 5;
            a0 = ldcg4(ap + kb + aqc);
            a1 = ldcg4(ap + kb + aqc + 16);
            const float* wp = W + (size_t)(kb + brow) * N;
            b0 = ldg4(wp + bqc);
            b1 = ldg4(wp + bqc + 32);
        }

        const float* As = sbase + p * STAGE_F;
        const float* Bs = As + 2176;
        #pragma unroll
        for (int kk = 0; kk < 32; kk++) {
            float4 av = *(const float4*)&As[kk * 68 + ty * 4];
            float4 bv = *(const float4*)&Bs[kk * 68 + tx * 4];
            unsigned long long bb01 = pack2(bv.x, bv.y);
            unsigned long long bb23 = pack2(bv.z, bv.w);
            unsigned long long am;
            am = pack2(av.x, av.x); ffma2(acc[0][0], am, bb01); ffma2(acc[0][1], am, bb23);
            am = pack2(av.y, av.y); ffma2(acc[1][0], am, bb01); ffma2(acc[1][1], am, bb23);
            am = pack2(av.z, av.z); ffma2(acc[2][0], am, bb01); ffma2(acc[2][1], am, bb23);
            am = pack2(av.w, av.w); ffma2(acc[3][0], am, bb01); ffma2(acc[3][1], am, bb23);
        }

        if (t + 1 < T) {
            // store prefetched tile into the other stage (its old readers all
            // finished before the sync that ended iteration t-1)
            float* Aw = sbase + (1 - p) * STAGE_F;
            float* Bw = Aw + 2176;
            Aw[(aqc + 0) * 68 + arow] = a0.x;  Aw[(aqc + 1) * 68 + arow] = a0.y;
            Aw[(aqc + 2) * 68 + arow] = a0.z;  Aw[(aqc + 3) * 68 + arow] = a0.w;
            Aw[(aqc + 16) * 68 + arow] = a1.x; Aw[(aqc + 17) * 68 + arow] = a1.y;
            Aw[(aqc + 18) * 68 + arow] = a1.z; Aw[(aqc + 19) * 68 + arow] = a1.w;
            *(float4*)&Bw[brow * 68 + bqc]      = b0;
            *(float4*)&Bw[brow * 68 + bqc + 32] = b1;
            half_sync(half);
            p ^= 1;
        }
    }

    #pragma unroll
    for (int m = 0; m < 4; m++) {
        float2 c0 = unpack2(acc[m][0]);
        float2 c1 = unpack2(acc[m][1]);
        stcg4(Pout + (size_t)(ty * 4 + m) * N + tx * 4,
              make_float4(c0.x, c0.y, c1.x, c1.y));
    }
}

// X1 slot tables. Pairs: p0=[e1|e2], p1=[e0|e2], p2=[e0|e1]
__device__ __constant__ int D1ROW[3] = {1, 0, 0};
__device__ __constant__ int D1OFF[3] = {0, 0, 768};
__device__ __constant__ int D2ROW[3] = {2, 2, 1};
__device__ __constant__ int D2OFF[3] = {0, 768, 768};

// ---------------------------------------------------------------------------
// Phase jobs (per 256-thread half)
// ---------------------------------------------------------------------------
__device__ void maxpool_job(int half, int t, float* sbase, int bk,
                            const float* __restrict__ enc,
                            const int* __restrict__ ep,
                            const float* __restrict__ projW,
                            const float* __restrict__ projb,
                            float* __restrict__ out_score)
{
    float* red = sbase;
    int b = bk / 3, k = bk - b * 3;
    int s0 = ep[bk * 2 + 0];
    int s1 = ep[bk * 2 + 1];

    float m0 = -1e30f, m1 = -1e30f, m2 = -1e30f;
    const float* base = enc + (size_t)b * SEQ * DIM;
    #pragma unroll 4
    for (int s = s0; s <= s1; s++) {
        const float* row = base + s * DIM;
        m0 = fmaxf(m0, __ldg(row + t));
        m1 = fmaxf(m1, __ldg(row + t + 256));
        m2 = fmaxf(m2, __ldg(row + t + 512));
    }

    size_t x1a = (size_t)(D1ROW[k] * 64 + b) * KDIM + D1OFF[k];
    size_t x1b = (size_t)(D2ROW[k] * 64 + b) * KDIM + D2OFF[k];
    size_t x2r = (size_t)(k * 64 + b) * KDIM + 768;
    size_t er  = (size_t)(k * 64 + b) * DIM;
    size_t eno = (size_t)b * PREDK + k * DIM;

    #pragma unroll
    for (int q = 0; q < 3; q++) {
        int d = t + q * 256;
        float m = (q == 0) ? m0 : (q == 1) ? m1 : m2;
        __stcg(g_ent + eno + d, m);
        __stcg(g_e   + er  + d, m);
        __stcg(g_X1  + x1a + d, m);
        __stcg(g_X1  + x1b + d, m);
        __stcg(g_X2  + x2r + d, m);
    }

    half_sync(half);                    // smem may be in use by prior job
    red[t] = m0 * projW[t] + m1 * projW[t + 256] + m2 * projW[t + 512];
    half_sync(half);
    for (int off = 128; off > 0; off >>= 1) {
        if (t < off) red[t] += red[t + off];
        half_sync(half);
    }
    if (t == 0) out_score[bk] = sigmoidf(red[0] + projb[0]);
    half_sync(half);
}

__device__ void finish1_job(int half, int t, float* sbase, int r,
                            const float* __restrict__ b1,
                            const float* __restrict__ W2, const float* __restrict__ b2,
                            const float* __restrict__ ArW, const float* __restrict__ Arb)
{
    float* sh_h = sbase;               // 512
    float* red  = sbase + 512;         // 5*256
    float* sh_s = sbase + 512 + 1280;  // 8

    half_sync(half);                   // protect smem from previous job
    for (int j = t; j < 512; j += 256) {
        float s = b1[j];
        #pragma unroll
        for (int z = 0; z < KS_FC1; z++)
            s += __ldcg(g_pfc1 + (size_t)z * FC1_MN + r * 512 + j);
        sh_h[j] = fmaxf(s, 0.0f);
    }
    half_sync(half);

    float ps[5] = {0, 0, 0, 0, 0};
    for (int j = t; j < 512; j += 256) {
        float h = sh_h[j];
        #pragma unroll
        for (int c = 0; c < 5; c++) ps[c] += h * W2[j * 5 + c];
    }
    #pragma unroll
    for (int c = 0; c < 5; c++) red[c * 256 + t] = ps[c];
    half_sync(half);
    for (int off = 128; off > 0; off >>= 1) {
        if (t < off) {
            #pragma unroll
            for (int c = 0; c < 5; c++) red[c * 256 + t] += red[c * 256 + t + off];
        }
        half_sync(half);
    }
    if (t < 5) sh_s[t] = sigmoidf(red[t * 256] + b2[t]);
    half_sync(half);

    float s0 = sh_s[0], s1 = sh_s[1], s2 = sh_s[2], s3 = sh_s[3], s4 = sh_s[4];
    const float* epv = g_e + (size_t)r * DIM;
    float* up = g_X2 + (size_t)r * KDIM;          // u -> left half of X2
    for (int d = t; d < DIM; d += 256) {
        float a = Arb[d] + s0 * ArW[d] + s1 * ArW[DIM + d] + s2 * ArW[2 * DIM + d]
                + s3 * ArW[3 * DIM + d] + s4 * ArW[4 * DIM + d];
        __stcg(up + d, a * __ldcg(epv + d));
    }
}

__device__ void pred_finish_job(int half, int t, float* sbase, int b,
                                const float* __restrict__ b1,
                                const float* __restrict__ W2,
                                const float* __restrict__ b2,
                                float* __restrict__ rel_out)
{
    float* sh_h = sbase;
    float* red  = sbase + 512;

    half_sync(half);
    for (int j = t; j < 512; j += 256) {
        float s = b1[j];
        #pragma unroll
        for (int z = 0; z < KS_PRED; z++)
            s += __ldcg(g_ppred + (size_t)z * PRED_MN + b * 512 + j);
        sh_h[j] = fmaxf(s, 0.0f);
    }
    half_sync(half);

    float ps[5] = {0, 0, 0, 0, 0};
    for (int j = t; j < 512; j += 256) {
        float h = sh_h[j];
        #pragma unroll
        for (int c = 0; c < 5; c++) ps[c] += h * W2[j * 5 + c];
    }
    #pragma unroll
    for (int c = 0; c < 5; c++) red[c * 256 + t] = ps[c];
    half_sync(half);
    for (int off = 128; off > 0; off >>= 1) {
        if (t < off) {
            #pragma unroll
            for (int c = 0; c < 5; c++) red[c * 256 + t] += red[c * 256 + t + off];
        }
        half_sync(half);
    }
    if (t < 5) rel_out[b * 5 + t] = red[t * 256] + b2[t];
}

// ---------------------------------------------------------------------------
// Persistent fused kernel: 512 threads = two 256-thread job workers
// ---------------------------------------------------------------------------
__global__ void __launch_bounds__(512, 1)
fused_kernel(const float* __restrict__ enc, const int* __restrict__ ep,
             const float* __restrict__ ArW, const float* __restrict__ Arb,
             const float* __restrict__ VrW1, const float* __restrict__ Vrb1,
             const float* __restrict__ VrW2, const float* __restrict__ Vrb2,
             const float* __restrict__ gateW, const float* __restrict__ gateb,
             const float* __restrict__ predW1, const float* __restrict__ predb1,
             const float* __restrict__ predW2, const float* __restrict__ predb2,
             const float* __restrict__ projW, const float* __restrict__ projb,
             float* __restrict__ out_rel, float* __restrict__ out_score,
             float* __restrict__ out_final)
{
    extern __shared__ __align__(16) float smem_u[];

    const int half = threadIdx.x >> 8;
    const int ht   = threadIdx.x & 255;
    float* sbase = smem_u + half * HALF_SMEM_F;

    const int gid     = blockIdx.x * 2 + half;     // worker id
    const int gstride = gridDim.x * 2;             // 296 workers

    // ---- Phase 0: span max-pool (+ scores, X1/X2 init) ----
    for (int job = gid; job < R192; job += gstride)
        maxpool_job(half, ht, sbase, job, enc, ep, projW, projb, out_score);
    grid_sync();

    for (int it = 0; it < 5; it++) {
        // ---- P1: fc1 GEMM partials (288 jobs) + pred GEMM (96 jobs, iter 0) ----
        int nj = (it == 0) ? (288 + 96) : 288;
        for (int job = gid; job < nj; job += gstride) {
            if (job < 288) {
                int z = job / 24, rem = job % 24;
                int m0 = (rem >> 3) * 64, n0 = (rem & 7) * 64;
                int k0 = z * 128;
                gemm_tile(half, ht, sbase,
                          g_X1 + (size_t)m0 * KDIM + k0, KDIM,
                          VrW1 + (size_t)k0 * 512 + n0, 512,
                          g_pfc1 + (size_t)z * FC1_MN + m0 * 512 + n0, 128);
            } else {
                int j = job - 288;                 // 0..95
                int z = j >> 3, n0 = (j & 7) * 64;
                int k0 = z * 192;
                gemm_tile(half, ht, sbase,
                          g_ent + k0, PREDK,
                          predW1 + (size_t)k0 * 512 + n0, 512,
                          g_ppred + (size_t)z * PRED_MN + n0, 192);
            }
        }
        grid_sync();

        // ---- P2: fc1 finish -> u (+ pred finish on iter 0) ----
        nj = (it == 0) ? 256 : 192;
        for (int job = gid; job < nj; job += gstride) {
            if (job < 192) finish1_job(half, ht, sbase, job, Vrb1, VrW2, Vrb2, ArW, Arb);
            else           pred_finish_job(half, ht, sbase, job - 192,
                                           predb1, predW2, predb2, out_rel);
        }
        grid_sync();

        // ---- P3: gate GEMM partials (288 jobs) ----
        for (int job = gid; job < 288; job += gstride) {
            int z = job / 36, rem = job % 36;
            int m0 = (rem / 12) * 64, n0 = (rem % 12) * 64;
            int k0 = z * 192;
            gemm_tile(half, ht, sbase,
                      g_X2 + (size_t)m0 * KDIM + k0, KDIM,
                      gateW + (size_t)k0 * 768 + n0, 768,
                      g_pgate + (size_t)z * GATE_MN + m0 * 768 + n0, 192);
        }
        grid_sync();

        // ---- P4: gate blend; in-place e update + X1/X2 scatter ----
        bool last = (it == 4);
        int tg = blockIdx.x * 512 + threadIdx.x;
        for (int q = tg; q < GATE_MN / 4; q += gridDim.x * 512) {
            int idx = q * 4;
            int r = idx / 768, n = idx - r * 768;
            int p = r >> 6, b = r & 63;
            float4 s = *(const float4*)(gateb + n);
            #pragma unroll
            for (int z = 0; z < KS_GATE; z++) {
                float4 pv = ldcg4(g_pgate + (size_t)z * GATE_MN + idx);
                s.x += pv.x; s.y += pv.y; s.z += pv.z; s.w += pv.w;
            }
            float4 uv = ldcg4(g_X2 + (size_t)r * KDIM + n);   // u (left half)
            float4 ev = ldcg4(g_e + idx);
            float4 res; float gg;
            gg = sigmoidf(s.x); res.x = gg * ev.x + (1.0f - gg) * uv.x;
            gg = sigmoidf(s.y); res.y = gg * ev.y + (1.0f - gg) * uv.y;
            gg = sigmoidf(s.z); res.z = gg * ev.z + (1.0f - gg) * uv.z;
            gg = sigmoidf(s.w); res.w = gg * ev.w + (1.0f - gg) * uv.w;
            if (last) {
                *(float4*)(out_final + (size_t)b * PREDK + p * DIM + n) = res;
            } else {
                stcg4(g_e + idx, res);
                stcg4(g_X2 + (size_t)r * KDIM + 768 + n, res);
                stcg4(g_X1 + (size_t)(D1ROW[p] * 64 + b) * KDIM + D1OFF[p] + n, res);
                stcg4(g_X1 + (size_t)(D2ROW[p] * 64 + b) * KDIM + D2OFF[p] + n, res);
            }
        }
        if (!last) grid_sync();
    }
}

// ---------------------------------------------------------------------------
// Launcher
// ---------------------------------------------------------------------------
extern "C" void kernel_launch(void* const* d_in, const int* in_sizes, int n_in,
                              void* d_out, int out_size)
{
    const float* encoding = (const float*)d_in[0];
    const int*   ent_pos  = (const int*)  d_in[1];
    const float* Ar_W     = (const float*)d_in[2];
    const float* Ar_b     = (const float*)d_in[3];
    const float* Vr_W1    = (const float*)d_in[4];
    const float* Vr_b1    = (const float*)d_in[5];
    const float* Vr_W2    = (const float*)d_in[6];
    const float* Vr_b2    = (const float*)d_in[7];
    const float* gate_W   = (const float*)d_in[8];
    const float* gate_b   = (const float*)d_in[9];
    const float* pred_W1  = (const float*)d_in[10];
    const float* pred_b1  = (const float*)d_in[11];
    const float* pred_W2  = (const float*)d_in[12];
    const float* pred_b2  = (const float*)d_in[13];
    const float* proj_W   = (const float*)d_in[14];
    const float* proj_b   = (const float*)d_in[15];

    float* out = (float*)d_out;
    float* out_rel   = out;              // (64,5)
    float* out_score = out + 320;        // (64,3)
    float* out_final = out + 512;        // (64,3,768)

    int dev = 0;
    cudaGetDevice(&dev);
    int sms = 148;
    cudaDeviceGetAttribute(&sms, cudaDevAttrMultiProcessorCount, dev);

    cudaFuncSetAttribute(fused_kernel,
                         cudaFuncAttributeMaxDynamicSharedMemorySize,
                         TOTAL_SMEM_B);

    fused_kernel<<<sms, 512, TOTAL_SMEM_B>>>(
        encoding, ent_pos, Ar_W, Ar_b,
        Vr_W1, Vr_b1, Vr_W2, Vr_b2,
        gate_W, gate_b,
        pred_W1, pred_b1, pred_W2, pred_b2,
        proj_W, proj_b,
        out_rel, out_score, out_final);

    (void)in_sizes; (void)n_in; (void)out_size;
}